// round 9
// baseline (speedup 1.0000x reference)
#include <cuda_runtime.h>
#include <cuda_bf16.h>
#include <cstdint>

#define Bb 32
#define Cc 512
#define Nn 1024
#define Oo 512

// ---------------------------------------------------------------------------
// Static device scratch (no runtime allocation)
// ---------------------------------------------------------------------------
__device__ float g_q[Bb * Nn];
__device__ float g_k[Bb * Nn];
__device__ __nv_bfloat16 g_xh[(size_t)Bb * Cc * Nn];     // 32 MB
__device__ __nv_bfloat16 g_xl[(size_t)Bb * Cc * Nn];     // 32 MB
__device__ __nv_bfloat16 g_wmh[Oo * Cc];
__device__ __nv_bfloat16 g_wml[Oo * Cc];
__device__ __nv_bfloat16 g_atth[(size_t)Bb * Nn * Nn];   // 64 MB
__device__ __nv_bfloat16 g_attl[(size_t)Bb * Nn * Nn];   // 64 MB
__device__ __nv_bfloat16 g_aggth[(size_t)Bb * Nn * Cc];  // 32 MB  [b][m][c]
__device__ __nv_bfloat16 g_aggtl[(size_t)Bb * Nn * Cc];  // 32 MB

// ---------------------------------------------------------------------------
// Family-stable PTX helpers (sm_80+): cp.async, ldmatrix, mma.sync
// ---------------------------------------------------------------------------
__device__ __forceinline__ uint32_t smem_u32(const void* p) {
    uint32_t a;
    asm("{ .reg .u64 t; cvta.to.shared.u64 t, %1; cvt.u32.u64 %0, t; }" : "=r"(a) : "l"(p));
    return a;
}
__device__ __forceinline__ void cp16(uint32_t sm, const void* g) {
    asm volatile("cp.async.cg.shared.global [%0], [%1], 16;" :: "r"(sm), "l"(g) : "memory");
}
#define CPASYNC_COMMIT() asm volatile("cp.async.commit_group;" ::: "memory")
#define CPASYNC_WAIT2()  asm volatile("cp.async.wait_group 2;" ::: "memory")

__device__ __forceinline__ void ldsm4(uint32_t* r, uint32_t addr) {
    asm volatile("ldmatrix.sync.aligned.m8n8.x4.shared.b16 {%0,%1,%2,%3}, [%4];"
                 : "=r"(r[0]), "=r"(r[1]), "=r"(r[2]), "=r"(r[3]) : "r"(addr));
}
__device__ __forceinline__ void mma_bf16(float* c, const uint32_t* a, uint32_t b0, uint32_t b1) {
    asm volatile(
        "mma.sync.aligned.m16n8k16.row.col.f32.bf16.bf16.f32 "
        "{%0,%1,%2,%3}, {%4,%5,%6,%7}, {%8,%9}, {%0,%1,%2,%3};"
        : "+f"(c[0]), "+f"(c[1]), "+f"(c[2]), "+f"(c[3])
        : "r"(a[0]), "r"(a[1]), "r"(a[2]), "r"(a[3]), "r"(b0), "r"(b1));
}

// ---------------------------------------------------------------------------
// smem tile geometry: 128 rows x 16 bf16 (32B) padded to 48B rows
// 48B stride -> 8-row phases hit 16B-banks {0,3,6,1,4,7,2,5}: conflict-free
// ---------------------------------------------------------------------------
#define LDSB 48                        // bytes per smem row
#define MATB (128 * LDSB)              // 6144 B per matrix
#define STAGEB (4 * MATB)              // Ah, Al, Bh, Bl = 24576 B
#define NSTAGE 4
#define GEMM_SMEM (NSTAGE * STAGEB)    // 98304 B -> 2 CTAs/SM

// load one 128x16 tile (2x16B chunks per row); 256 cp16 / 256 threads
__device__ __forceinline__ void load_tile16(uint32_t dst, const __nv_bfloat16* g,
                                            int ld, int k0, int tid) {
    int row = tid >> 1, ch = tid & 1;
    cp16(dst + row * LDSB + ch * 16, g + (size_t)row * ld + k0 + ch * 8);
}

// ---------------------------------------------------------------------------
// mainloop: acc[i][j][*] += sum_k A[m][k]*B[n][k] via 3-term bf16 split
// BK=16, 4-stage ring, prefetch distance 3, wait_group 2:
//   awaited group was committed 3 chunks earlier -> wait rarely blocks
// ---------------------------------------------------------------------------
__device__ __forceinline__ void gemm_mainloop(
    float acc[4][4][4], uint32_t smem,
    const __nv_bfloat16* Ah, const __nv_bfloat16* Al, int lda,
    const __nv_bfloat16* Bh, const __nv_bfloat16* Bl, int ldb,
    int K, int tid)
{
    const int nch = K / 16;
    const int lane = tid & 31, wid = tid >> 5;
    const int wm = wid >> 2, wn = wid & 3;

    const uint32_t arow = (uint32_t)((wm * 64 + (lane & 15)) * LDSB + (lane >> 4) * 16);
    const uint32_t brow = (uint32_t)((wn * 32 + (lane & 15)) * LDSB + (lane >> 4) * 16);

    // prologue: prefetch chunks 0..2 into stages 0..2
#pragma unroll
    for (int p = 0; p < 3; p++) {
        uint32_t st = smem + p * STAGEB;
        load_tile16(st + 0 * MATB, Ah, lda, p * 16, tid);
        load_tile16(st + 1 * MATB, Al, lda, p * 16, tid);
        load_tile16(st + 2 * MATB, Bh, ldb, p * 16, tid);
        load_tile16(st + 3 * MATB, Bl, ldb, p * 16, tid);
        CPASYNC_COMMIT();
    }

    for (int ch = 0; ch < nch; ch++) {
        CPASYNC_WAIT2();          // group for chunk ch retired (3-deep pipeline)
        __syncthreads();          // all warps done with stage being refilled (ch-1's)

        int pf = ch + 3;
        if (pf < nch) {
            uint32_t st = smem + (pf & 3) * STAGEB;
            int k0 = pf * 16;
            load_tile16(st + 0 * MATB, Ah, lda, k0, tid);
            load_tile16(st + 1 * MATB, Al, lda, k0, tid);
            load_tile16(st + 2 * MATB, Bh, ldb, k0, tid);
            load_tile16(st + 3 * MATB, Bl, ldb, k0, tid);
        }
        CPASYNC_COMMIT();         // commit every iteration to keep group count aligned

        uint32_t cur = smem + (ch & 3) * STAGEB;

        uint32_t aH[4][4], aL[4][4], bH[2][4], bL[2][4];
#pragma unroll
        for (int i = 0; i < 4; i++)
            ldsm4(aH[i], cur + 0 * MATB + arow + i * (16 * LDSB));
#pragma unroll
        for (int i = 0; i < 4; i++)
            ldsm4(aL[i], cur + 1 * MATB + arow + i * (16 * LDSB));
#pragma unroll
        for (int p = 0; p < 2; p++)
            ldsm4(bH[p], cur + 2 * MATB + brow + p * (16 * LDSB));
#pragma unroll
        for (int p = 0; p < 2; p++)
            ldsm4(bL[p], cur + 3 * MATB + brow + p * (16 * LDSB));

#pragma unroll
        for (int i = 0; i < 4; i++) {
#pragma unroll
            for (int j = 0; j < 4; j++) {
                const uint32_t* bh = bH[j >> 1];
                const uint32_t* bl = bL[j >> 1];
                uint32_t h0 = bh[j & 1], h1 = bh[(j & 1) + 2];
                uint32_t l0 = bl[j & 1], l1 = bl[(j & 1) + 2];
                mma_bf16(acc[i][j], aH[i], h0, h1);   // Ah*Bh
                mma_bf16(acc[i][j], aH[i], l0, l1);   // Ah*Bl
                mma_bf16(acc[i][j], aL[i], h0, h1);   // Al*Bh
            }
        }
    }
}

// ---------------------------------------------------------------------------
// Kernel: f32 -> bf16 hi/lo split (elementwise) — for wm only
// ---------------------------------------------------------------------------
__global__ void split_kernel(const float* __restrict__ src,
                             __nv_bfloat16* __restrict__ hi,
                             __nv_bfloat16* __restrict__ lo) {
    size_t i = (size_t)blockIdx.x * blockDim.x + threadIdx.x;
    float v = src[i];
    __nv_bfloat16 h = __float2bfloat16(v);
    hi[i] = h;
    lo[i] = __float2bfloat16(v - __bfloat162float(h));
}

// ---------------------------------------------------------------------------
// Kernel 1 (fused): q/k projections + x hi/lo split (single pass over x)
// ---------------------------------------------------------------------------
__global__ void qk_split_kernel(const float* __restrict__ x,
                                const float* __restrict__ wq,
                                const float* __restrict__ wk) {
    int idx = blockIdx.x * blockDim.x + threadIdx.x;   // b*Nn + n
    int b = idx / Nn;
    int n = idx % Nn;
    size_t base = (size_t)b * Cc * Nn + n;
    const float* xb = x + base;
    __nv_bfloat16* xh = g_xh + base;
    __nv_bfloat16* xl = g_xl + base;
    float q = 0.f, k = 0.f;
#pragma unroll 4
    for (int c = 0; c < Cc; c++) {
        float v = xb[(size_t)c * Nn];
        q = fmaf(__ldg(&wq[c]), v, q);
        k = fmaf(__ldg(&wk[c]), v, k);
        __nv_bfloat16 h = __float2bfloat16(v);
        xh[(size_t)c * Nn] = h;
        xl[(size_t)c * Nn] = __float2bfloat16(v - __bfloat162float(h));
    }
    g_q[idx] = q;
    g_k[idx] = k;
}

// ---------------------------------------------------------------------------
// Kernel 2: att[b,i,:] = softmax_j( leaky( q[b,j] + k[b,i] ) ) -> bf16 hi/lo
// ---------------------------------------------------------------------------
__device__ __forceinline__ float warp_max(float v) {
#pragma unroll
    for (int o = 16; o > 0; o >>= 1) v = fmaxf(v, __shfl_xor_sync(0xffffffffu, v, o));
    return v;
}
__device__ __forceinline__ float warp_sum(float v) {
#pragma unroll
    for (int o = 16; o > 0; o >>= 1) v += __shfl_xor_sync(0xffffffffu, v, o);
    return v;
}

__global__ void softmax_kernel() {
    int row = blockIdx.x;            // b*Nn + i
    int b = row / Nn;
    const float4* qb4 = (const float4*)(g_q + (size_t)b * Nn);
    float kv = g_k[row];
    __nv_bfloat16* oh = g_atth + (size_t)row * Nn;
    __nv_bfloat16* ol = g_attl + (size_t)row * Nn;

    int t = threadIdx.x;
    int lane = t & 31, wid = t >> 5;
    __shared__ float red[8];

    float4 qv = qb4[t];
    float vals[4] = {qv.x + kv, qv.y + kv, qv.z + kv, qv.w + kv};
    float mx = -1e30f;
#pragma unroll
    for (int u = 0; u < 4; u++) {
        float s = vals[u];
        s = s > 0.f ? s : 0.01f * s;  // LeakyReLU
        vals[u] = s;
        mx = fmaxf(mx, s);
    }
    mx = warp_max(mx);
    if (lane == 0) red[wid] = mx;
    __syncthreads();
    if (wid == 0) {
        float v = (lane < 8) ? red[lane] : -1e30f;
        v = warp_max(v);
        if (lane == 0) red[0] = v;
    }
    __syncthreads();
    mx = red[0];
    __syncthreads();

    float sum = 0.f;
#pragma unroll
    for (int u = 0; u < 4; u++) {
        vals[u] = __expf(vals[u] - mx);
        sum += vals[u];
    }
    sum = warp_sum(sum);
    if (lane == 0) red[wid] = sum;
    __syncthreads();
    if (wid == 0) {
        float v = (lane < 8) ? red[lane] : 0.f;
        v = warp_sum(v);
        if (lane == 0) red[0] = v;
    }
    __syncthreads();
    float inv = 1.0f / red[0];

    float v0 = vals[0] * inv, v1 = vals[1] * inv, v2 = vals[2] * inv, v3 = vals[3] * inv;
    __nv_bfloat16 h0 = __float2bfloat16(v0), h1 = __float2bfloat16(v1);
    __nv_bfloat16 h2 = __float2bfloat16(v2), h3 = __float2bfloat16(v3);
    __nv_bfloat162 hp0(h0, h1), hp1(h2, h3);
    __nv_bfloat162 lp0(__float2bfloat16(v0 - __bfloat162float(h0)),
                       __float2bfloat16(v1 - __bfloat162float(h1)));
    __nv_bfloat162 lp1(__float2bfloat16(v2 - __bfloat162float(h2)),
                       __float2bfloat16(v3 - __bfloat162float(h3)));
    uint2 hu = make_uint2(*(uint32_t*)&hp0, *(uint32_t*)&hp1);
    uint2 lu = make_uint2(*(uint32_t*)&lp0, *(uint32_t*)&lp1);
    *(uint2*)(oh + 4 * t) = hu;
    *(uint2*)(ol + 4 * t) = lu;
}

// ---------------------------------------------------------------------------
// GEMM1: D[m][c] = sum_n att[b][m][n] * x[b][c][n]  -> agg_t[b][m][c] hi/lo
// grid: (Cc/128, Nn/128, Bb)
// ---------------------------------------------------------------------------
__global__ __launch_bounds__(256, 2)
void gemm1_kernel() {
    extern __shared__ char smem[];
    uint32_t sbase = smem_u32(smem);
    int tid = threadIdx.x;
    int c0 = blockIdx.x * 128, m0 = blockIdx.y * 128, b = blockIdx.z;

    const __nv_bfloat16* Ah = g_atth + (size_t)b * Nn * Nn + (size_t)m0 * Nn;
    const __nv_bfloat16* Al = g_attl + (size_t)b * Nn * Nn + (size_t)m0 * Nn;
    const __nv_bfloat16* Bh = g_xh + (size_t)b * Cc * Nn + (size_t)c0 * Nn;
    const __nv_bfloat16* Bl = g_xl + (size_t)b * Cc * Nn + (size_t)c0 * Nn;

    float acc[4][4][4];
#pragma unroll
    for (int i = 0; i < 4; i++)
#pragma unroll
        for (int j = 0; j < 4; j++)
#pragma unroll
            for (int r = 0; r < 4; r++) acc[i][j][r] = 0.f;

    gemm_mainloop(acc, sbase, Ah, Al, Nn, Bh, Bl, Nn, Nn, tid);

    int lane = tid & 31, wid = tid >> 5;
    int wm = wid >> 2, wn = wid & 3;
    size_t base = (size_t)b * Nn * Cc;
#pragma unroll
    for (int i = 0; i < 4; i++) {
#pragma unroll
        for (int j = 0; j < 4; j++) {
            int r = m0 + wm * 64 + i * 16 + (lane >> 2);
            int c = c0 + wn * 32 + j * 8 + (lane & 3) * 2;
#pragma unroll
            for (int half = 0; half < 2; half++) {
                int rr = r + half * 8;
                float v0 = acc[i][j][half * 2 + 0];
                float v1 = acc[i][j][half * 2 + 1];
                __nv_bfloat16 h0 = __float2bfloat16(v0);
                __nv_bfloat16 h1 = __float2bfloat16(v1);
                __nv_bfloat16 l0 = __float2bfloat16(v0 - __bfloat162float(h0));
                __nv_bfloat16 l1 = __float2bfloat16(v1 - __bfloat162float(h1));
                size_t off = base + (size_t)rr * Cc + c;
                *(__nv_bfloat162*)(g_aggth + off) = __nv_bfloat162(h0, h1);
                *(__nv_bfloat162*)(g_aggtl + off) = __nv_bfloat162(l0, l1);
            }
        }
    }
}

// ---------------------------------------------------------------------------
// GEMM2: D[o][m] = sum_c wm[o][c] * agg_t[b][m][c]; out = relu(D + bm[o])
// grid: (Nn/128, Oo/128, Bb)
// ---------------------------------------------------------------------------
__global__ __launch_bounds__(256, 2)
void gemm2_kernel(float* __restrict__ out, const float* __restrict__ bias) {
    extern __shared__ char smem[];
    uint32_t sbase = smem_u32(smem);
    int tid = threadIdx.x;
    int mm0 = blockIdx.x * 128, o0 = blockIdx.y * 128, b = blockIdx.z;

    const __nv_bfloat16* Ah = g_wmh + (size_t)o0 * Cc;
    const __nv_bfloat16* Al = g_wml + (size_t)o0 * Cc;
    const __nv_bfloat16* Bh = g_aggth + (size_t)b * Nn * Cc + (size_t)mm0 * Cc;
    const __nv_bfloat16* Bl = g_aggtl + (size_t)b * Nn * Cc + (size_t)mm0 * Cc;

    float acc[4][4][4];
#pragma unroll
    for (int i = 0; i < 4; i++)
#pragma unroll
        for (int j = 0; j < 4; j++)
#pragma unroll
            for (int r = 0; r < 4; r++) acc[i][j][r] = 0.f;

    gemm_mainloop(acc, sbase, Ah, Al, Cc, Bh, Bl, Cc, Cc, tid);

    int lane = tid & 31, wid = tid >> 5;
    int wm = wid >> 2, wn = wid & 3;
    float* ob = out + (size_t)b * Oo * Nn;
#pragma unroll
    for (int i = 0; i < 4; i++) {
#pragma unroll
        for (int j = 0; j < 4; j++) {
            int o = o0 + wm * 64 + i * 16 + (lane >> 2);
            int m = mm0 + wn * 32 + j * 8 + (lane & 3) * 2;
#pragma unroll
            for (int half = 0; half < 2; half++) {
                int oo = o + half * 8;
                float bv = __ldg(&bias[oo]);
                float v0 = acc[i][j][half * 2 + 0] + bv;
                float v1 = acc[i][j][half * 2 + 1] + bv;
                v0 = v0 > 0.f ? v0 : 0.f;
                v1 = v1 > 0.f ? v1 : 0.f;
                *(float2*)(ob + (size_t)oo * Nn + m) = make_float2(v0, v1);
            }
        }
    }
}

// ---------------------------------------------------------------------------
extern "C" void kernel_launch(void* const* d_in, const int* in_sizes, int n_in,
                              void* d_out, int out_size) {
    const float* x  = (const float*)d_in[0];
    const float* wq = (const float*)d_in[1];
    const float* wk = (const float*)d_in[2];
    const float* wm = (const float*)d_in[3];
    const float* bm = (const float*)d_in[4];
    float* out = (float*)d_out;

    __nv_bfloat16 *wmh, *wml;
    cudaGetSymbolAddress((void**)&wmh, g_wmh);
    cudaGetSymbolAddress((void**)&wml, g_wml);

    cudaFuncSetAttribute(gemm1_kernel, cudaFuncAttributeMaxDynamicSharedMemorySize, GEMM_SMEM);
    cudaFuncSetAttribute(gemm2_kernel, cudaFuncAttributeMaxDynamicSharedMemorySize, GEMM_SMEM);

    // 1) wm split + fused qk/x-split (x read once)
    split_kernel<<<(Oo * Cc) / 256, 256>>>(wm, wmh, wml);
    qk_split_kernel<<<(Bb * Nn) / 256, 256>>>(x, wq, wk);

    // 2) leaky + softmax -> att bf16 hi/lo
    softmax_kernel<<<Bb * Nn, 256>>>();

    // 3) GEMM1 (HMMA): agg_t[b][m][c] hi/lo
    {
        dim3 grid(Cc / 128, Nn / 128, Bb);
        gemm1_kernel<<<grid, 256, GEMM_SMEM>>>();
    }

    // 4) GEMM2 (HMMA): out = relu(wm @ agg + bm)
    {
        dim3 grid(Nn / 128, Oo / 128, Bb);
        gemm2_kernel<<<grid, 256, GEMM_SMEM>>>(out, bm);
    }
}

// round 12
// speedup vs baseline: 1.0422x; 1.0422x over previous
#include <cuda_runtime.h>
#include <cuda_bf16.h>
#include <cstdint>

#define Bb 32
#define Cc 512
#define Nn 1024
#define Oo 512

// ---------------------------------------------------------------------------
// Static device scratch (no runtime allocation)
// ---------------------------------------------------------------------------
__device__ float g_q[Bb * Nn];
__device__ float g_k[Bb * Nn];
__device__ __nv_bfloat16 g_xh[(size_t)Bb * Cc * Nn];     // 32 MB
__device__ __nv_bfloat16 g_xl[(size_t)Bb * Cc * Nn];     // 32 MB
__device__ __nv_bfloat16 g_wmh[Oo * Cc];
__device__ __nv_bfloat16 g_wml[Oo * Cc];
__device__ __nv_bfloat16 g_atth[(size_t)Bb * Nn * Nn];   // 64 MB
__device__ __nv_bfloat16 g_attl[(size_t)Bb * Nn * Nn];   // 64 MB
__device__ __nv_bfloat16 g_aggth[(size_t)Bb * Nn * Cc];  // 32 MB  [b][m][c]
__device__ __nv_bfloat16 g_aggtl[(size_t)Bb * Nn * Cc];  // 32 MB

// ---------------------------------------------------------------------------
// Family-stable PTX helpers (sm_80+): cp.async, ldmatrix, mma.sync
// ---------------------------------------------------------------------------
__device__ __forceinline__ uint32_t smem_u32(const void* p) {
    uint32_t a;
    asm("{ .reg .u64 t; cvta.to.shared.u64 t, %1; cvt.u32.u64 %0, t; }" : "=r"(a) : "l"(p));
    return a;
}
__device__ __forceinline__ void cp16(uint32_t sm, const void* g) {
    asm volatile("cp.async.cg.shared.global [%0], [%1], 16;" :: "r"(sm), "l"(g) : "memory");
}
#define CPASYNC_COMMIT() asm volatile("cp.async.commit_group;" ::: "memory")
#define CPASYNC_WAIT0()  asm volatile("cp.async.wait_group 0;" ::: "memory")

__device__ __forceinline__ void ldsm4(uint32_t* r, uint32_t addr) {
    asm volatile("ldmatrix.sync.aligned.m8n8.x4.shared.b16 {%0,%1,%2,%3}, [%4];"
                 : "=r"(r[0]), "=r"(r[1]), "=r"(r[2]), "=r"(r[3]) : "r"(addr));
}
__device__ __forceinline__ void mma_bf16(float* c, const uint32_t* a, uint32_t b0, uint32_t b1) {
    asm volatile(
        "mma.sync.aligned.m16n8k16.row.col.f32.bf16.bf16.f32 "
        "{%0,%1,%2,%3}, {%4,%5,%6,%7}, {%8,%9}, {%0,%1,%2,%3};"
        : "+f"(c[0]), "+f"(c[1]), "+f"(c[2]), "+f"(c[3])
        : "r"(a[0]), "r"(a[1]), "r"(a[2]), "r"(a[3]), "r"(b0), "r"(b1));
}

// one term-pass: 16 independent accumulators, no RAW between consecutive mma
__device__ __forceinline__ void mma_term(float acc[4][4][4],
                                         const uint32_t a[4][4],
                                         const uint32_t b[2][4]) {
#pragma unroll
    for (int i = 0; i < 4; i++)
#pragma unroll
        for (int j = 0; j < 4; j++) {
            const uint32_t* bp = b[j >> 1];
            mma_bf16(acc[i][j], a[i], bp[j & 1], bp[(j & 1) + 2]);
        }
}

// ---------------------------------------------------------------------------
// smem tile geometry: 128 rows x 32 bf16, padded row stride 40 bf16 (80 B)
// ---------------------------------------------------------------------------
#define LDSB 80                       // bytes per smem row
#define MATB (128 * LDSB)             // 10240 B per matrix
#define STAGEB (4 * MATB)             // Ah, Al, Bh, Bl = 40960 B
#define NSTAGE 2
#define GEMM_SMEM (NSTAGE * STAGEB)   // 81920 B -> 2 CTAs/SM

// load one 128x32 tile (4x16B chunks per row) via cp.async; 512 chunks/256 thr
__device__ __forceinline__ void load_tile32(uint32_t dst, const __nv_bfloat16* g,
                                            int ld, int k0, int tid) {
    int row0 = tid >> 2;
    int ch = tid & 3;
    cp16(dst + row0 * LDSB + ch * 16, g + (size_t)row0 * ld + (k0 + ch * 8));
    int row1 = row0 + 64;
    cp16(dst + row1 * LDSB + ch * 16, g + (size_t)row1 * ld + (k0 + ch * 8));
}

// ---------------------------------------------------------------------------
// mainloop: acc[i][j][*] += sum_k A[m][k]*B[n][k] via 3-term bf16 split
// 2-stage ring, prefetch distance 1, ONE __syncthreads per K-chunk.
// MMA order is TERM-MAJOR (mma_term): same accumulator revisited only after
// 16 independent mma -> no accumulator RAW stalls.
// ---------------------------------------------------------------------------
__device__ __forceinline__ void gemm_mainloop(
    float acc[4][4][4], uint32_t smem,
    const __nv_bfloat16* Ah, const __nv_bfloat16* Al, int lda,
    const __nv_bfloat16* Bh, const __nv_bfloat16* Bl, int ldb,
    int K, int tid)
{
    const int nch = K / 32;
    const int lane = tid & 31, wid = tid >> 5;
    const int wm = wid >> 2, wn = wid & 3;

    const uint32_t arow = (uint32_t)((wm * 64 + (lane & 15)) * LDSB + (lane >> 4) * 16);
    const uint32_t brow = (uint32_t)((wn * 32 + (lane & 15)) * LDSB + (lane >> 4) * 16);

    // prologue: prefetch chunk 0 into stage 0
    load_tile32(smem + 0 * MATB, Ah, lda, 0, tid);
    load_tile32(smem + 1 * MATB, Al, lda, 0, tid);
    load_tile32(smem + 2 * MATB, Bh, ldb, 0, tid);
    load_tile32(smem + 3 * MATB, Bl, ldb, 0, tid);
    CPASYNC_COMMIT();

    for (int ch = 0; ch < nch; ch++) {
        CPASYNC_WAIT0();          // chunk ch resident
        __syncthreads();          // all warps done with stage being refilled

        int pf = ch + 1;
        if (pf < nch) {
            uint32_t st = smem + (pf & 1) * STAGEB;
            int k0 = pf * 32;
            load_tile32(st + 0 * MATB, Ah, lda, k0, tid);
            load_tile32(st + 1 * MATB, Al, lda, k0, tid);
            load_tile32(st + 2 * MATB, Bh, ldb, k0, tid);
            load_tile32(st + 3 * MATB, Bl, ldb, k0, tid);
        }
        CPASYNC_COMMIT();

        uint32_t cur = smem + (ch & 1) * STAGEB;

#pragma unroll
        for (int s = 0; s < 2; s++) {       // two k16 steps inside BK=32
            uint32_t aH[4][4], aL[4][4], bH[2][4], bL[2][4];
            uint32_t abase = cur + arow + s * 32;
            uint32_t bbase = cur + brow + s * 32;
#pragma unroll
            for (int i = 0; i < 4; i++)
                ldsm4(aH[i], abase + 0 * MATB + i * (16 * LDSB));
#pragma unroll
            for (int i = 0; i < 4; i++)
                ldsm4(aL[i], abase + 1 * MATB + i * (16 * LDSB));
#pragma unroll
            for (int p = 0; p < 2; p++)
                ldsm4(bH[p], bbase + 2 * MATB + p * (16 * LDSB));
#pragma unroll
            for (int p = 0; p < 2; p++)
                ldsm4(bL[p], bbase + 3 * MATB + p * (16 * LDSB));

            mma_term(acc, aH, bH);   // term 1: Ah*Bh
            mma_term(acc, aH, bL);   // term 2: Ah*Bl
            mma_term(acc, aL, bH);   // term 3: Al*Bh
        }
    }
}

// ---------------------------------------------------------------------------
// Kernel: f32 -> bf16 hi/lo split (elementwise) — for wm only
// ---------------------------------------------------------------------------
__global__ void split_kernel(const float* __restrict__ src,
                             __nv_bfloat16* __restrict__ hi,
                             __nv_bfloat16* __restrict__ lo) {
    size_t i = (size_t)blockIdx.x * blockDim.x + threadIdx.x;
    float v = src[i];
    __nv_bfloat16 h = __float2bfloat16(v);
    hi[i] = h;
    lo[i] = __float2bfloat16(v - __bfloat162float(h));
}

// ---------------------------------------------------------------------------
// Kernel 1 (fused): q/k projections + x hi/lo split (single pass over x)
// ---------------------------------------------------------------------------
__global__ void qk_split_kernel(const float* __restrict__ x,
                                const float* __restrict__ wq,
                                const float* __restrict__ wk) {
    int idx = blockIdx.x * blockDim.x + threadIdx.x;   // b*Nn + n
    int b = idx / Nn;
    int n = idx % Nn;
    size_t base = (size_t)b * Cc * Nn + n;
    const float* xb = x + base;
    __nv_bfloat16* xh = g_xh + base;
    __nv_bfloat16* xl = g_xl + base;
    float q = 0.f, k = 0.f;
#pragma unroll 4
    for (int c = 0; c < Cc; c++) {
        float v = xb[(size_t)c * Nn];
        q = fmaf(__ldg(&wq[c]), v, q);
        k = fmaf(__ldg(&wk[c]), v, k);
        __nv_bfloat16 h = __float2bfloat16(v);
        xh[(size_t)c * Nn] = h;
        xl[(size_t)c * Nn] = __float2bfloat16(v - __bfloat162float(h));
    }
    g_q[idx] = q;
    g_k[idx] = k;
}

// ---------------------------------------------------------------------------
// Kernel 2: att[b,i,:] = softmax_j( leaky( q[b,j] + k[b,i] ) ) -> bf16 hi/lo
// ---------------------------------------------------------------------------
__device__ __forceinline__ float warp_max(float v) {
#pragma unroll
    for (int o = 16; o > 0; o >>= 1) v = fmaxf(v, __shfl_xor_sync(0xffffffffu, v, o));
    return v;
}
__device__ __forceinline__ float warp_sum(float v) {
#pragma unroll
    for (int o = 16; o > 0; o >>= 1) v += __shfl_xor_sync(0xffffffffu, v, o);
    return v;
}

__global__ void softmax_kernel() {
    int row = blockIdx.x;            // b*Nn + i
    int b = row / Nn;
    const float4* qb4 = (const float4*)(g_q + (size_t)b * Nn);
    float kv = g_k[row];
    __nv_bfloat16* oh = g_atth + (size_t)row * Nn;
    __nv_bfloat16* ol = g_attl + (size_t)row * Nn;

    int t = threadIdx.x;
    int lane = t & 31, wid = t >> 5;
    __shared__ float red[8];

    float4 qv = qb4[t];
    float vals[4] = {qv.x + kv, qv.y + kv, qv.z + kv, qv.w + kv};
    float mx = -1e30f;
#pragma unroll
    for (int u = 0; u < 4; u++) {
        float s = vals[u];
        s = s > 0.f ? s : 0.01f * s;  // LeakyReLU
        vals[u] = s;
        mx = fmaxf(mx, s);
    }
    mx = warp_max(mx);
    if (lane == 0) red[wid] = mx;
    __syncthreads();
    if (wid == 0) {
        float v = (lane < 8) ? red[lane] : -1e30f;
        v = warp_max(v);
        if (lane == 0) red[0] = v;
    }
    __syncthreads();
    mx = red[0];
    __syncthreads();

    float sum = 0.f;
#pragma unroll
    for (int u = 0; u < 4; u++) {
        vals[u] = __expf(vals[u] - mx);
        sum += vals[u];
    }
    sum = warp_sum(sum);
    if (lane == 0) red[wid] = sum;
    __syncthreads();
    if (wid == 0) {
        float v = (lane < 8) ? red[lane] : 0.f;
        v = warp_sum(v);
        if (lane == 0) red[0] = v;
    }
    __syncthreads();
    float inv = 1.0f / red[0];

    float v0 = vals[0] * inv, v1 = vals[1] * inv, v2 = vals[2] * inv, v3 = vals[3] * inv;
    __nv_bfloat16 h0 = __float2bfloat16(v0), h1 = __float2bfloat16(v1);
    __nv_bfloat16 h2 = __float2bfloat16(v2), h3 = __float2bfloat16(v3);
    __nv_bfloat162 hp0(h0, h1), hp1(h2, h3);
    __nv_bfloat162 lp0(__float2bfloat16(v0 - __bfloat162float(h0)),
                       __float2bfloat16(v1 - __bfloat162float(h1)));
    __nv_bfloat162 lp1(__float2bfloat16(v2 - __bfloat162float(h2)),
                       __float2bfloat16(v3 - __bfloat162float(h3)));
    uint2 hu = make_uint2(*(uint32_t*)&hp0, *(uint32_t*)&hp1);
    uint2 lu = make_uint2(*(uint32_t*)&lp0, *(uint32_t*)&lp1);
    *(uint2*)(oh + 4 * t) = hu;
    *(uint2*)(ol + 4 * t) = lu;
}

// ---------------------------------------------------------------------------
// GEMM1: D[m][c] = sum_n att[b][m][n] * x[b][c][n]  -> agg_t[b][m][c] hi/lo
// grid: (Cc/128, Nn/128, Bb)
// ---------------------------------------------------------------------------
__global__ __launch_bounds__(256, 2)
void gemm1_kernel() {
    extern __shared__ char smem[];
    uint32_t sbase = smem_u32(smem);
    int tid = threadIdx.x;
    int c0 = blockIdx.x * 128, m0 = blockIdx.y * 128, b = blockIdx.z;

    const __nv_bfloat16* Ah = g_atth + (size_t)b * Nn * Nn + (size_t)m0 * Nn;
    const __nv_bfloat16* Al = g_attl + (size_t)b * Nn * Nn + (size_t)m0 * Nn;
    const __nv_bfloat16* Bh = g_xh + (size_t)b * Cc * Nn + (size_t)c0 * Nn;
    const __nv_bfloat16* Bl = g_xl + (size_t)b * Cc * Nn + (size_t)c0 * Nn;

    float acc[4][4][4];
#pragma unroll
    for (int i = 0; i < 4; i++)
#pragma unroll
        for (int j = 0; j < 4; j++)
#pragma unroll
            for (int r = 0; r < 4; r++) acc[i][j][r] = 0.f;

    gemm_mainloop(acc, sbase, Ah, Al, Nn, Bh, Bl, Nn, Nn, tid);

    int lane = tid & 31, wid = tid >> 5;
    int wm = wid >> 2, wn = wid & 3;
    size_t base = (size_t)b * Nn * Cc;
#pragma unroll
    for (int i = 0; i < 4; i++) {
#pragma unroll
        for (int j = 0; j < 4; j++) {
            int r = m0 + wm * 64 + i * 16 + (lane >> 2);
            int c = c0 + wn * 32 + j * 8 + (lane & 3) * 2;
#pragma unroll
            for (int half = 0; half < 2; half++) {
                int rr = r + half * 8;
                float v0 = acc[i][j][half * 2 + 0];
                float v1 = acc[i][j][half * 2 + 1];
                __nv_bfloat16 h0 = __float2bfloat16(v0);
                __nv_bfloat16 h1 = __float2bfloat16(v1);
                __nv_bfloat16 l0 = __float2bfloat16(v0 - __bfloat162float(h0));
                __nv_bfloat16 l1 = __float2bfloat16(v1 - __bfloat162float(h1));
                size_t off = base + (size_t)rr * Cc + c;
                *(__nv_bfloat162*)(g_aggth + off) = __nv_bfloat162(h0, h1);
                *(__nv_bfloat162*)(g_aggtl + off) = __nv_bfloat162(l0, l1);
            }
        }
    }
}

// ---------------------------------------------------------------------------
// GEMM2: D[o][m] = sum_c wm[o][c] * agg_t[b][m][c]; out = relu(D + bm[o])
// grid: (Nn/128, Oo/128, Bb)
// ---------------------------------------------------------------------------
__global__ __launch_bounds__(256, 2)
void gemm2_kernel(float* __restrict__ out, const float* __restrict__ bias) {
    extern __shared__ char smem[];
    uint32_t sbase = smem_u32(smem);
    int tid = threadIdx.x;
    int mm0 = blockIdx.x * 128, o0 = blockIdx.y * 128, b = blockIdx.z;

    const __nv_bfloat16* Ah = g_wmh + (size_t)o0 * Cc;
    const __nv_bfloat16* Al = g_wml + (size_t)o0 * Cc;
    const __nv_bfloat16* Bh = g_aggth + (size_t)b * Nn * Cc + (size_t)mm0 * Cc;
    const __nv_bfloat16* Bl = g_aggtl + (size_t)b * Nn * Cc + (size_t)mm0 * Cc;

    float acc[4][4][4];
#pragma unroll
    for (int i = 0; i < 4; i++)
#pragma unroll
        for (int j = 0; j < 4; j++)
#pragma unroll
            for (int r = 0; r < 4; r++) acc[i][j][r] = 0.f;

    gemm_mainloop(acc, sbase, Ah, Al, Cc, Bh, Bl, Cc, Cc, tid);

    int lane = tid & 31, wid = tid >> 5;
    int wm = wid >> 2, wn = wid & 3;
    float* ob = out + (size_t)b * Oo * Nn;
#pragma unroll
    for (int i = 0; i < 4; i++) {
#pragma unroll
        for (int j = 0; j < 4; j++) {
            int o = o0 + wm * 64 + i * 16 + (lane >> 2);
            int m = mm0 + wn * 32 + j * 8 + (lane & 3) * 2;
#pragma unroll
            for (int half = 0; half < 2; half++) {
                int oo = o + half * 8;
                float bv = __ldg(&bias[oo]);
                float v0 = acc[i][j][half * 2 + 0] + bv;
                float v1 = acc[i][j][half * 2 + 1] + bv;
                v0 = v0 > 0.f ? v0 : 0.f;
                v1 = v1 > 0.f ? v1 : 0.f;
                *(float2*)(ob + (size_t)oo * Nn + m) = make_float2(v0, v1);
            }
        }
    }
}

// ---------------------------------------------------------------------------
extern "C" void kernel_launch(void* const* d_in, const int* in_sizes, int n_in,
                              void* d_out, int out_size) {
    const float* x  = (const float*)d_in[0];
    const float* wq = (const float*)d_in[1];
    const float* wk = (const float*)d_in[2];
    const float* wm = (const float*)d_in[3];
    const float* bm = (const float*)d_in[4];
    float* out = (float*)d_out;

    __nv_bfloat16 *wmh, *wml;
    cudaGetSymbolAddress((void**)&wmh, g_wmh);
    cudaGetSymbolAddress((void**)&wml, g_wml);

    cudaFuncSetAttribute(gemm1_kernel, cudaFuncAttributeMaxDynamicSharedMemorySize, GEMM_SMEM);
    cudaFuncSetAttribute(gemm2_kernel, cudaFuncAttributeMaxDynamicSharedMemorySize, GEMM_SMEM);

    // 1) wm split + fused qk/x-split (x read once)
    split_kernel<<<(Oo * Cc) / 256, 256>>>(wm, wmh, wml);
    qk_split_kernel<<<(Bb * Nn) / 256, 256>>>(x, wq, wk);

    // 2) leaky + softmax -> att bf16 hi/lo
    softmax_kernel<<<Bb * Nn, 256>>>();

    // 3) GEMM1 (HMMA): agg_t[b][m][c] hi/lo
    {
        dim3 grid(Cc / 128, Nn / 128, Bb);
        gemm1_kernel<<<grid, 256, GEMM_SMEM>>>();
    }

    // 4) GEMM2 (HMMA): out = relu(wm @ agg + bm)
    {
        dim3 grid(Nn / 128, Oo / 128, Bb);
        gemm2_kernel<<<grid, 256, GEMM_SMEM>>>(out, bm);
    }
}

// round 13
// speedup vs baseline: 1.0511x; 1.0086x over previous
#include <cuda_runtime.h>
#include <cuda_bf16.h>
#include <cstdint>

#define Bb 32
#define Cc 512
#define Nn 1024
#define Oo 512

// ---------------------------------------------------------------------------
// Static device scratch (no runtime allocation)
// ---------------------------------------------------------------------------
__device__ float g_q[Bb * Nn];
__device__ float g_k[Bb * Nn];
__device__ __nv_bfloat16 g_xh[(size_t)Bb * Cc * Nn];     // 32 MB
__device__ __nv_bfloat16 g_xl[(size_t)Bb * Cc * Nn];     // 32 MB
__device__ __nv_bfloat16 g_wmh[Oo * Cc];
__device__ __nv_bfloat16 g_wml[Oo * Cc];
__device__ __nv_bfloat16 g_atth[(size_t)Bb * Nn * Nn];   // 64 MB
__device__ __nv_bfloat16 g_attl[(size_t)Bb * Nn * Nn];   // 64 MB
__device__ __nv_bfloat16 g_aggth[(size_t)Bb * Nn * Cc];  // 32 MB  [b][m][c]
__device__ __nv_bfloat16 g_aggtl[(size_t)Bb * Nn * Cc];  // 32 MB

// ---------------------------------------------------------------------------
// Family-stable PTX helpers (sm_80+): cp.async, ldmatrix, mma.sync
// ---------------------------------------------------------------------------
__device__ __forceinline__ uint32_t smem_u32(const void* p) {
    uint32_t a;
    asm("{ .reg .u64 t; cvta.to.shared.u64 t, %1; cvt.u32.u64 %0, t; }" : "=r"(a) : "l"(p));
    return a;
}
__device__ __forceinline__ void cp16(uint32_t sm, const void* g) {
    asm volatile("cp.async.cg.shared.global [%0], [%1], 16;" :: "r"(sm), "l"(g) : "memory");
}
#define CPASYNC_COMMIT() asm volatile("cp.async.commit_group;" ::: "memory")
#define CPASYNC_WAIT0()  asm volatile("cp.async.wait_group 0;" ::: "memory")

// ldsm stays volatile: smem stage addresses repeat every 2 chunks, and without
// volatile the compiler could CSE fragments across ring wrap (unsound).
__device__ __forceinline__ void ldsm4(uint32_t* r, uint32_t addr) {
    asm volatile("ldmatrix.sync.aligned.m8n8.x4.shared.b16 {%0,%1,%2,%3}, [%4];"
                 : "=r"(r[0]), "=r"(r[1]), "=r"(r[2]), "=r"(r[3]) : "r"(addr));
}
// NON-volatile mma: pure register computation; ordering is fully captured by
// data dependencies. Lets nvcc/ptxas interleave mma with ldsm bursts.
__device__ __forceinline__ void mma_bf16(float* c, const uint32_t* a, uint32_t b0, uint32_t b1) {
    asm("mma.sync.aligned.m16n8k16.row.col.f32.bf16.bf16.f32 "
        "{%0,%1,%2,%3}, {%4,%5,%6,%7}, {%8,%9}, {%0,%1,%2,%3};"
        : "+f"(c[0]), "+f"(c[1]), "+f"(c[2]), "+f"(c[3])
        : "r"(a[0]), "r"(a[1]), "r"(a[2]), "r"(a[3]), "r"(b0), "r"(b1));
}

// 4 mma of one A-row fragment against 4 column pairs of a B fragment set
__device__ __forceinline__ void mma_row(float accr[4][4],
                                        const uint32_t a[4],
                                        const uint32_t b[2][4]) {
#pragma unroll
    for (int j = 0; j < 4; j++) {
        const uint32_t* bp = b[j >> 1];
        mma_bf16(accr[j], a, bp[j & 1], bp[(j & 1) + 2]);
    }
}

// ---------------------------------------------------------------------------
// smem tile geometry: 128 rows x 32 bf16, padded row stride 40 bf16 (80 B)
// ---------------------------------------------------------------------------
#define LDSB 80                       // bytes per smem row
#define MATB (128 * LDSB)             // 10240 B per matrix
#define STAGEB (4 * MATB)             // Ah, Al, Bh, Bl = 40960 B
#define NSTAGE 2
#define GEMM_SMEM (NSTAGE * STAGEB)   // 81920 B -> 2 CTAs/SM

// load one 128x32 tile (4x16B chunks per row) via cp.async; 512 chunks/256 thr
__device__ __forceinline__ void load_tile32(uint32_t dst, const __nv_bfloat16* g,
                                            int ld, int k0, int tid) {
    int row0 = tid >> 2;
    int ch = tid & 3;
    cp16(dst + row0 * LDSB + ch * 16, g + (size_t)row0 * ld + (k0 + ch * 8));
    int row1 = row0 + 64;
    cp16(dst + row1 * LDSB + ch * 16, g + (size_t)row1 * ld + (k0 + ch * 8));
}

// ---------------------------------------------------------------------------
// mainloop: acc[i][j][*] += sum_k A[m][k]*B[n][k] via 3-term bf16 split
// 2-stage ring, prefetch distance 1, ONE __syncthreads per K-chunk.
// ldsm and mma manually interleaved so memory latency hides under mma issue.
// ---------------------------------------------------------------------------
__device__ __forceinline__ void gemm_mainloop(
    float acc[4][4][4], uint32_t smem,
    const __nv_bfloat16* Ah, const __nv_bfloat16* Al, int lda,
    const __nv_bfloat16* Bh, const __nv_bfloat16* Bl, int ldb,
    int K, int tid)
{
    const int nch = K / 32;
    const int lane = tid & 31, wid = tid >> 5;
    const int wm = wid >> 2, wn = wid & 3;

    const uint32_t arow = (uint32_t)((wm * 64 + (lane & 15)) * LDSB + (lane >> 4) * 16);
    const uint32_t brow = (uint32_t)((wn * 32 + (lane & 15)) * LDSB + (lane >> 4) * 16);

    // prologue: prefetch chunk 0 into stage 0
    load_tile32(smem + 0 * MATB, Ah, lda, 0, tid);
    load_tile32(smem + 1 * MATB, Al, lda, 0, tid);
    load_tile32(smem + 2 * MATB, Bh, ldb, 0, tid);
    load_tile32(smem + 3 * MATB, Bl, ldb, 0, tid);
    CPASYNC_COMMIT();

    for (int ch = 0; ch < nch; ch++) {
        CPASYNC_WAIT0();          // chunk ch resident
        __syncthreads();          // all warps done with stage being refilled

        int pf = ch + 1;
        if (pf < nch) {
            uint32_t st = smem + (pf & 1) * STAGEB;
            int k0 = pf * 32;
            load_tile32(st + 0 * MATB, Ah, lda, k0, tid);
            load_tile32(st + 1 * MATB, Al, lda, k0, tid);
            load_tile32(st + 2 * MATB, Bh, ldb, k0, tid);
            load_tile32(st + 3 * MATB, Bl, ldb, k0, tid);
        }
        CPASYNC_COMMIT();

        uint32_t cur = smem + (ch & 1) * STAGEB;

#pragma unroll
        for (int s = 0; s < 2; s++) {       // two k16 steps inside BK=32
            uint32_t aH[4][4], aL[4][4], bH[2][4], bL[2][4];
            uint32_t abase = cur + arow + s * 32;
            uint32_t bbase = cur + brow + s * 32;

            // B fragments first (needed by every term)
            ldsm4(bH[0], bbase + 2 * MATB);
            ldsm4(bH[1], bbase + 2 * MATB + 16 * LDSB);
            ldsm4(bL[0], bbase + 3 * MATB);
            ldsm4(bL[1], bbase + 3 * MATB + 16 * LDSB);

            // term 1 (Ah*Bh), row-by-row: each row's mma can start while
            // later rows' ldsm are still in flight
#pragma unroll
            for (int i = 0; i < 4; i++) {
                ldsm4(aH[i], abase + 0 * MATB + i * (16 * LDSB));
                mma_row(acc[i], aH[i], bH);
            }
            // term 2 (Ah*Bl) interleaved with aL loads
#pragma unroll
            for (int i = 0; i < 4; i++) {
                ldsm4(aL[i], abase + 1 * MATB + i * (16 * LDSB));
                mma_row(acc[i], aH[i], bL);
            }
            // term 3 (Al*Bh)
#pragma unroll
            for (int i = 0; i < 4; i++)
                mma_row(acc[i], aL[i], bH);
        }
    }
}

// ---------------------------------------------------------------------------
// Kernel: f32 -> bf16 hi/lo split (elementwise) — for wm only
// ---------------------------------------------------------------------------
__global__ void split_kernel(const float* __restrict__ src,
                             __nv_bfloat16* __restrict__ hi,
                             __nv_bfloat16* __restrict__ lo) {
    size_t i = (size_t)blockIdx.x * blockDim.x + threadIdx.x;
    float v = src[i];
    __nv_bfloat16 h = __float2bfloat16(v);
    hi[i] = h;
    lo[i] = __float2bfloat16(v - __bfloat162float(h));
}

// ---------------------------------------------------------------------------
// Kernel 1 (fused): q/k projections + x hi/lo split (single pass over x)
// ---------------------------------------------------------------------------
__global__ void qk_split_kernel(const float* __restrict__ x,
                                const float* __restrict__ wq,
                                const float* __restrict__ wk) {
    int idx = blockIdx.x * blockDim.x + threadIdx.x;   // b*Nn + n
    int b = idx / Nn;
    int n = idx % Nn;
    size_t base = (size_t)b * Cc * Nn + n;
    const float* xb = x + base;
    __nv_bfloat16* xh = g_xh + base;
    __nv_bfloat16* xl = g_xl + base;
    float q = 0.f, k = 0.f;
#pragma unroll 4
    for (int c = 0; c < Cc; c++) {
        float v = xb[(size_t)c * Nn];
        q = fmaf(__ldg(&wq[c]), v, q);
        k = fmaf(__ldg(&wk[c]), v, k);
        __nv_bfloat16 h = __float2bfloat16(v);
        xh[(size_t)c * Nn] = h;
        xl[(size_t)c * Nn] = __float2bfloat16(v - __bfloat162float(h));
    }
    g_q[idx] = q;
    g_k[idx] = k;
}

// ---------------------------------------------------------------------------
// Kernel 2: att[b,i,:] = softmax_j( leaky( q[b,j] + k[b,i] ) ) -> bf16 hi/lo
// ---------------------------------------------------------------------------
__device__ __forceinline__ float warp_max(float v) {
#pragma unroll
    for (int o = 16; o > 0; o >>= 1) v = fmaxf(v, __shfl_xor_sync(0xffffffffu, v, o));
    return v;
}
__device__ __forceinline__ float warp_sum(float v) {
#pragma unroll
    for (int o = 16; o > 0; o >>= 1) v += __shfl_xor_sync(0xffffffffu, v, o);
    return v;
}

__global__ void softmax_kernel() {
    int row = blockIdx.x;            // b*Nn + i
    int b = row / Nn;
    const float4* qb4 = (const float4*)(g_q + (size_t)b * Nn);
    float kv = g_k[row];
    __nv_bfloat16* oh = g_atth + (size_t)row * Nn;
    __nv_bfloat16* ol = g_attl + (size_t)row * Nn;

    int t = threadIdx.x;
    int lane = t & 31, wid = t >> 5;
    __shared__ float red[8];

    float4 qv = qb4[t];
    float vals[4] = {qv.x + kv, qv.y + kv, qv.z + kv, qv.w + kv};
    float mx = -1e30f;
#pragma unroll
    for (int u = 0; u < 4; u++) {
        float s = vals[u];
        s = s > 0.f ? s : 0.01f * s;  // LeakyReLU
        vals[u] = s;
        mx = fmaxf(mx, s);
    }
    mx = warp_max(mx);
    if (lane == 0) red[wid] = mx;
    __syncthreads();
    if (wid == 0) {
        float v = (lane < 8) ? red[lane] : -1e30f;
        v = warp_max(v);
        if (lane == 0) red[0] = v;
    }
    __syncthreads();
    mx = red[0];
    __syncthreads();

    float sum = 0.f;
#pragma unroll
    for (int u = 0; u < 4; u++) {
        vals[u] = __expf(vals[u] - mx);
        sum += vals[u];
    }
    sum = warp_sum(sum);
    if (lane == 0) red[wid] = sum;
    __syncthreads();
    if (wid == 0) {
        float v = (lane < 8) ? red[lane] : 0.f;
        v = warp_sum(v);
        if (lane == 0) red[0] = v;
    }
    __syncthreads();
    float inv = 1.0f / red[0];

    float v0 = vals[0] * inv, v1 = vals[1] * inv, v2 = vals[2] * inv, v3 = vals[3] * inv;
    __nv_bfloat16 h0 = __float2bfloat16(v0), h1 = __float2bfloat16(v1);
    __nv_bfloat16 h2 = __float2bfloat16(v2), h3 = __float2bfloat16(v3);
    __nv_bfloat162 hp0(h0, h1), hp1(h2, h3);
    __nv_bfloat162 lp0(__float2bfloat16(v0 - __bfloat162float(h0)),
                       __float2bfloat16(v1 - __bfloat162float(h1)));
    __nv_bfloat162 lp1(__float2bfloat16(v2 - __bfloat162float(h2)),
                       __float2bfloat16(v3 - __bfloat162float(h3)));
    uint2 hu = make_uint2(*(uint32_t*)&hp0, *(uint32_t*)&hp1);
    uint2 lu = make_uint2(*(uint32_t*)&lp0, *(uint32_t*)&lp1);
    *(uint2*)(oh + 4 * t) = hu;
    *(uint2*)(ol + 4 * t) = lu;
}

// ---------------------------------------------------------------------------
// GEMM1: D[m][c] = sum_n att[b][m][n] * x[b][c][n]  -> agg_t[b][m][c] hi/lo
// grid: (Cc/128, Nn/128, Bb)
// ---------------------------------------------------------------------------
__global__ __launch_bounds__(256, 2)
void gemm1_kernel() {
    extern __shared__ char smem[];
    uint32_t sbase = smem_u32(smem);
    int tid = threadIdx.x;
    int c0 = blockIdx.x * 128, m0 = blockIdx.y * 128, b = blockIdx.z;

    const __nv_bfloat16* Ah = g_atth + (size_t)b * Nn * Nn + (size_t)m0 * Nn;
    const __nv_bfloat16* Al = g_attl + (size_t)b * Nn * Nn + (size_t)m0 * Nn;
    const __nv_bfloat16* Bh = g_xh + (size_t)b * Cc * Nn + (size_t)c0 * Nn;
    const __nv_bfloat16* Bl = g_xl + (size_t)b * Cc * Nn + (size_t)c0 * Nn;

    float acc[4][4][4];
#pragma unroll
    for (int i = 0; i < 4; i++)
#pragma unroll
        for (int j = 0; j < 4; j++)
#pragma unroll
            for (int r = 0; r < 4; r++) acc[i][j][r] = 0.f;

    gemm_mainloop(acc, sbase, Ah, Al, Nn, Bh, Bl, Nn, Nn, tid);

    int lane = tid & 31, wid = tid >> 5;
    int wm = wid >> 2, wn = wid & 3;
    size_t base = (size_t)b * Nn * Cc;
#pragma unroll
    for (int i = 0; i < 4; i++) {
#pragma unroll
        for (int j = 0; j < 4; j++) {
            int r = m0 + wm * 64 + i * 16 + (lane >> 2);
            int c = c0 + wn * 32 + j * 8 + (lane & 3) * 2;
#pragma unroll
            for (int half = 0; half < 2; half++) {
                int rr = r + half * 8;
                float v0 = acc[i][j][half * 2 + 0];
                float v1 = acc[i][j][half * 2 + 1];
                __nv_bfloat16 h0 = __float2bfloat16(v0);
                __nv_bfloat16 h1 = __float2bfloat16(v1);
                __nv_bfloat16 l0 = __float2bfloat16(v0 - __bfloat162float(h0));
                __nv_bfloat16 l1 = __float2bfloat16(v1 - __bfloat162float(h1));
                size_t off = base + (size_t)rr * Cc + c;
                *(__nv_bfloat162*)(g_aggth + off) = __nv_bfloat162(h0, h1);
                *(__nv_bfloat162*)(g_aggtl + off) = __nv_bfloat162(l0, l1);
            }
        }
    }
}

// ---------------------------------------------------------------------------
// GEMM2: D[o][m] = sum_c wm[o][c] * agg_t[b][m][c]; out = relu(D + bm[o])
// grid: (Nn/128, Oo/128, Bb)
// ---------------------------------------------------------------------------
__global__ __launch_bounds__(256, 2)
void gemm2_kernel(float* __restrict__ out, const float* __restrict__ bias) {
    extern __shared__ char smem[];
    uint32_t sbase = smem_u32(smem);
    int tid = threadIdx.x;
    int mm0 = blockIdx.x * 128, o0 = blockIdx.y * 128, b = blockIdx.z;

    const __nv_bfloat16* Ah = g_wmh + (size_t)o0 * Cc;
    const __nv_bfloat16* Al = g_wml + (size_t)o0 * Cc;
    const __nv_bfloat16* Bh = g_aggth + (size_t)b * Nn * Cc + (size_t)mm0 * Cc;
    const __nv_bfloat16* Bl = g_aggtl + (size_t)b * Nn * Cc + (size_t)mm0 * Cc;

    float acc[4][4][4];
#pragma unroll
    for (int i = 0; i < 4; i++)
#pragma unroll
        for (int j = 0; j < 4; j++)
#pragma unroll
            for (int r = 0; r < 4; r++) acc[i][j][r] = 0.f;

    gemm_mainloop(acc, sbase, Ah, Al, Cc, Bh, Bl, Cc, Cc, tid);

    int lane = tid & 31, wid = tid >> 5;
    int wm = wid >> 2, wn = wid & 3;
    float* ob = out + (size_t)b * Oo * Nn;
#pragma unroll
    for (int i = 0; i < 4; i++) {
#pragma unroll
        for (int j = 0; j < 4; j++) {
            int o = o0 + wm * 64 + i * 16 + (lane >> 2);
            int m = mm0 + wn * 32 + j * 8 + (lane & 3) * 2;
#pragma unroll
            for (int half = 0; half < 2; half++) {
                int oo = o + half * 8;
                float bv = __ldg(&bias[oo]);
                float v0 = acc[i][j][half * 2 + 0] + bv;
                float v1 = acc[i][j][half * 2 + 1] + bv;
                v0 = v0 > 0.f ? v0 : 0.f;
                v1 = v1 > 0.f ? v1 : 0.f;
                *(float2*)(ob + (size_t)oo * Nn + m) = make_float2(v0, v1);
            }
        }
    }
}

// ---------------------------------------------------------------------------
extern "C" void kernel_launch(void* const* d_in, const int* in_sizes, int n_in,
                              void* d_out, int out_size) {
    const float* x  = (const float*)d_in[0];
    const float* wq = (const float*)d_in[1];
    const float* wk = (const float*)d_in[2];
    const float* wm = (const float*)d_in[3];
    const float* bm = (const float*)d_in[4];
    float* out = (float*)d_out;

    __nv_bfloat16 *wmh, *wml;
    cudaGetSymbolAddress((void**)&wmh, g_wmh);
    cudaGetSymbolAddress((void**)&wml, g_wml);

    cudaFuncSetAttribute(gemm1_kernel, cudaFuncAttributeMaxDynamicSharedMemorySize, GEMM_SMEM);
    cudaFuncSetAttribute(gemm2_kernel, cudaFuncAttributeMaxDynamicSharedMemorySize, GEMM_SMEM);

    // 1) wm split + fused qk/x-split (x read once)
    split_kernel<<<(Oo * Cc) / 256, 256>>>(wm, wmh, wml);
    qk_split_kernel<<<(Bb * Nn) / 256, 256>>>(x, wq, wk);

    // 2) leaky + softmax -> att bf16 hi/lo
    softmax_kernel<<<Bb * Nn, 256>>>();

    // 3) GEMM1 (HMMA): agg_t[b][m][c] hi/lo
    {
        dim3 grid(Cc / 128, Nn / 128, Bb);
        gemm1_kernel<<<grid, 256, GEMM_SMEM>>>();
    }

    // 4) GEMM2 (HMMA): out = relu(wm @ agg + bm)
    {
        dim3 grid(Nn / 128, Oo / 128, Bb);
        gemm2_kernel<<<grid, 256, GEMM_SMEM>>>(out, bm);
    }
}